// round 17
// baseline (speedup 1.0000x reference)
#include <cuda_runtime.h>
#include <cuda_fp16.h>
#include <cstdint>

#define N_NODES 50000
#define N_EDGES 800000
#define DIM 128
#define HEADS 8
#define THREADS 512

// ---- node GEMM config (R12+, unchanged) ----
#define NTILE_M 64
#define KTW_H 517                 // uint2 per k-tile for W (128 n * 4 + 5 pad)
#define KTA_H 261                 // uint2 per k-tile for node A (64 rows * 4 + 5 pad)
#define SMEM_W_U2 (8 * KTW_H)     // 4136 uint2 = 33088 B
#define SMEM_NA_U2 (8 * KTA_H)    // 2088 uint2 = 16704 B
#define NODE_SMEM ((SMEM_W_U2 + SMEM_NA_U2) * 8)   // 49792 B
#define GRID 296

// ---- edge kernel (warp-specialized): 48-edge tiles, 12 prod + 4 cons warps ----
#define ETILE 48
#define KTA48 197                 // uint2 per k-tile (48 rows * 4 + 5 pad)
#define SMEM_EA_U2 (8 * KTA48)    // 1576 uint2 = 12608 B
#define CS_H_STRIDE 136           // halves per Cs row (272 B)
#define CS_TILE_H (ETILE * CS_H_STRIDE)            // halves per Cs buffer
#define EDGE_SMEM ((SMEM_W_U2 + SMEM_EA_U2) * 8 + 2 * CS_TILE_H * 2)  // 71808 B

// Scratch (allocation-free rule: __device__ globals)
__device__ __half g_Q[N_NODES * DIM];
__device__ __half g_K[N_NODES * DIM];
__device__ __half g_V[N_NODES * DIM];
__device__ float  g_z[N_NODES * HEADS];

// ---------------------------------------------------------------------------
// helpers
// ---------------------------------------------------------------------------
__device__ __forceinline__ uint32_t pack_h2(float lo, float hi) {
    __half2 h = __floats2half2_rn(lo, hi);
    return *reinterpret_cast<uint32_t*>(&h);
}

__device__ __forceinline__ float4 unpack_h4(uint2 w) {
    float2 a = __half22float2(*reinterpret_cast<__half2*>(&w.x));
    float2 b = __half22float2(*reinterpret_cast<__half2*>(&w.y));
    return make_float4(a.x, a.y, b.x, b.y);
}

__device__ __forceinline__ void mma16(float c[4], uint32_t a0, uint32_t a1,
                                      uint32_t a2, uint32_t a3,
                                      uint32_t b0, uint32_t b1) {
    asm("mma.sync.aligned.m16n8k16.row.col.f32.f16.f16.f32 "
        "{%0,%1,%2,%3}, {%4,%5,%6,%7}, {%8,%9}, {%0,%1,%2,%3};\n"
        : "+f"(c[0]), "+f"(c[1]), "+f"(c[2]), "+f"(c[3])
        : "r"(a0), "r"(a1), "r"(a2), "r"(a3), "r"(b0), "r"(b1));
}

__device__ __forceinline__ void red_add_v4(float* p, float4 v) {
    asm volatile("red.global.add.v4.f32 [%0], {%1,%2,%3,%4};"
                 :: "l"(p), "f"(v.x), "f"(v.y), "f"(v.z), "f"(v.w));
}

__device__ __forceinline__ void red_add_f32(float* p, float v) {
    asm volatile("red.global.add.f32 [%0], %1;" :: "l"(p), "f"(v));
}

#define BAR_SYNC(id, cnt) \
    asm volatile("bar.sync %0, %1;" :: "r"(id), "r"(cnt) : "memory")
#define BAR_ARRIVE(id, cnt) \
    asm volatile("bar.arrive %0, %1;" :: "r"(id), "r"(cnt) : "memory")

// Stage W[128][128] (row-major k x n) into fp16 fragment layout.
__device__ __forceinline__ void stage_W(uint2* Wp, const float* __restrict__ W,
                                        int nthreads) {
    int tid = threadIdx.x;
#pragma unroll 1
    for (int idx = tid; idx < 4096; idx += nthreads) {
        int n = idx & 127;
        int rest = idx >> 7;
        int tp = rest & 3;
        int kt = rest >> 2;
        int k0 = kt * 16 + tp * 2;
        uint32_t lo = pack_h2(W[k0 * DIM + n], W[(k0 + 1) * DIM + n]);
        uint32_t hi = pack_h2(W[(k0 + 8) * DIM + n], W[(k0 + 9) * DIM + n]);
        Wp[kt * KTW_H + n * 4 + tp] = make_uint2(lo, hi);
    }
}

// ---------------------------------------------------------------------------
// edge kernel: warp-specialized producer/consumer
// ---------------------------------------------------------------------------
// producers (384 thr): thread owns row r = tid>>3 (0..47), ktile kt = tid&7
__device__ __forceinline__ void prefetch_E48(float4 v[4], const float* __restrict__ E,
                                             int row0, int tid) {
    int r = tid >> 3, kt = tid & 7;
    int grow = row0 + r;
    if (grow < N_EDGES) {
        const float4* p = (const float4*)&E[(size_t)grow * DIM + kt * 16];
#pragma unroll
        for (int i = 0; i < 4; ++i) v[i] = __ldcs(p + i);
    } else {
#pragma unroll
        for (int i = 0; i < 4; ++i) v[i] = make_float4(0.f, 0.f, 0.f, 0.f);
    }
}

__device__ __forceinline__ void store_E48(uint2* Ap, const float4 v[4], int tid) {
    int r = tid >> 3, kt = tid & 7;
    uint2* base = Ap + kt * KTA48 + r * 4;
    base[0] = make_uint2(pack_h2(v[0].x, v[0].y), pack_h2(v[2].x, v[2].y));
    base[1] = make_uint2(pack_h2(v[0].z, v[0].w), pack_h2(v[2].z, v[2].w));
    base[2] = make_uint2(pack_h2(v[1].x, v[1].y), pack_h2(v[3].x, v[3].y));
    base[3] = make_uint2(pack_h2(v[1].z, v[1].w), pack_h2(v[3].z, v[3].w));
}

__device__ __forceinline__ void mma_tile48(const uint2* Ap, const uint2* Wp,
                                           int wm, int wn, int lane,
                                           float c[4][4]) {
#pragma unroll
    for (int kt = 0; kt < 8; ++kt) {
        const uint2* ak = Ap + kt * KTA48;
        const uint2* wk = Wp + kt * KTW_H;
        uint2 aA = ak[wm * 4 + lane];
        uint2 aB = ak[(wm + 8) * 4 + lane];
#pragma unroll
        for (int nf = 0; nf < 4; ++nf) {
            uint2 b = wk[(wn + nf * 8) * 4 + lane];
            mma16(c[nf], aA.x, aB.x, aA.y, aB.y, b.x, b.y);
        }
    }
}

__global__ __launch_bounds__(THREADS, 2)
void gemm_edge(const float* __restrict__ Ein, const float* __restrict__ W,
               const float* __restrict__ bias, const int* __restrict__ src,
               const int* __restrict__ dst, float* __restrict__ hacc,
               float* __restrict__ eout) {
    extern __shared__ uint2 smem[];
    uint2* Wp = smem;
    uint2* Ap = smem + SMEM_W_U2;
    __half* Cs0 = (__half*)(smem + SMEM_W_U2 + SMEM_EA_U2);
    int tid = threadIdx.x, lane = tid & 31, warp = tid >> 5;

    stage_W(Wp, W, THREADS);
    float4 be4 = *(const float4*)&bias[lane * 4];
    __syncthreads();

    const int nTiles = (N_EDGES + ETILE - 1) / ETILE;  // 16667
    const int G = gridDim.x;

    if (warp < 12) {
        // ---------------- producers: GEMM into Cs ring ----------------
        int wm = (warp % 3) * 16, wn = (warp / 3) * 32;
        int g = lane >> 2, t = lane & 3;
        float4 cur[4];
        int tile = blockIdx.x;
        if (tile < nTiles) prefetch_E48(cur, Ein, tile * ETILE, tid);
        int i = 0;
#pragma unroll 1
        for (; tile < nTiles; tile += G, ++i) {
            int p = i & 1;
            if (i >= 2) BAR_SYNC(4 + p, 512);      // Cs[p] free (tile i-2 consumed)
            store_E48(Ap, cur, tid);
            BAR_SYNC(1, 384);                      // A staged by all producers
            float c[4][4];
#pragma unroll
            for (int j = 0; j < 4; ++j)
#pragma unroll
                for (int k = 0; k < 4; ++k) c[j][k] = 0.f;
            mma_tile48(Ap, Wp, wm, wn, lane, c);
            BAR_SYNC(6, 384);                      // all producers done reading A
            int nxt = tile + G;
            if (nxt < nTiles) prefetch_E48(cur, Ein, nxt * ETILE, tid);
            __half* Cs = Cs0 + p * CS_TILE_H;
            int rr = wm + g;
#pragma unroll
            for (int nf = 0; nf < 4; ++nf) {
                int col = wn + nf * 8 + t * 2;
                *(uint32_t*)&Cs[rr * CS_H_STRIDE + col] =
                    pack_h2(c[nf][0], c[nf][1]);
                *(uint32_t*)&Cs[(rr + 8) * CS_H_STRIDE + col] =
                    pack_h2(c[nf][2], c[nf][3]);
            }
            __threadfence_block();
            BAR_ARRIVE(2 + p, 512);                // Cs[p] full
        }
    } else {
        // ---------------- consumers: gather/score/scatter ----------------
        int cw = warp - 12;                        // 0..3, 12 edges each
        int tile = blockIdx.x;
        int i = 0;
#pragma unroll 1
        for (; tile < nTiles; tile += G, ++i) {
            int p = i & 1;
            BAR_SYNC(2 + p, 512);                  // wait Cs[p] full
            const __half* Cs = Cs0 + p * CS_TILE_H;
            int ebase = tile * ETILE + cw * 12;
#pragma unroll 1
            for (int i0 = 0; i0 < 12; i0 += 4) {
                int sn4[4], dn4[4];
                bool val[4];
#pragma unroll
                for (int j = 0; j < 4; ++j) {
                    int e = ebase + i0 + j;
                    val[j] = (e < N_EDGES);
                    sn4[j] = val[j] ? __ldg(&src[e]) : 0;
                    dn4[j] = val[j] ? __ldg(&dst[e]) : 0;
                }
                uint2 qr[4], kr[4], vr[4], wc[4];
#pragma unroll
                for (int j = 0; j < 4; ++j) {
                    qr[j] = *(const uint2*)&g_Q[(size_t)dn4[j] * DIM + lane * 4];
                    kr[j] = *(const uint2*)&g_K[(size_t)sn4[j] * DIM + lane * 4];
                    vr[j] = *(const uint2*)&g_V[(size_t)sn4[j] * DIM + lane * 4];
                    wc[j] = *(const uint2*)&Cs[(cw * 12 + i0 + j) * CS_H_STRIDE + lane * 4];
                }
#pragma unroll
                for (int j = 0; j < 4; ++j) {
                    float4 q = unpack_h4(qr[j]);
                    float4 kk = unpack_h4(kr[j]);
                    float4 vv = unpack_h4(vr[j]);
                    float4 cc = unpack_h4(wc[j]);
                    float4 pr = make_float4(cc.x + be4.x, cc.y + be4.y,
                                            cc.z + be4.z, cc.w + be4.w);
                    float4 sc;
                    sc.x = q.x * kk.x * 0.25f * pr.x;
                    sc.y = q.y * kk.y * 0.25f * pr.y;
                    sc.z = q.z * kk.z * 0.25f * pr.z;
                    sc.w = q.w * kk.w * 0.25f * pr.w;
                    if (val[j])
                        __stcs((float4*)&eout[(size_t)(ebase + i0 + j) * DIM + lane * 4], sc);
                    float hs = sc.x + sc.y + sc.z + sc.w;
                    hs += __shfl_xor_sync(0xffffffffu, hs, 1);
                    hs += __shfl_xor_sync(0xffffffffu, hs, 2);
                    float s = __expf(fminf(fmaxf(hs, -5.f), 5.f));
                    if (val[j]) {
                        red_add_v4(&hacc[(size_t)dn4[j] * DIM + lane * 4],
                                   make_float4(vv.x * s, vv.y * s, vv.z * s, vv.w * s));
                        if ((lane & 3) == 0)
                            red_add_f32(&g_z[dn4[j] * HEADS + (lane >> 2)], s);
                    }
                }
            }
            BAR_ARRIVE(4 + p, 512);                // Cs[p] free
        }
    }
}

// ---------------------------------------------------------------------------
// node-GEMM path (fp16 mma.sync, R14 passing version)
// ---------------------------------------------------------------------------
__device__ __forceinline__ void prefetch_nA(float4 v[4], const float* __restrict__ A,
                                            int row0, int M, int tid) {
    int r = tid >> 3, kt = tid & 7;
    int grow = row0 + r;
    if (grow < M) {
        const float4* p = (const float4*)&A[(size_t)grow * DIM + kt * 16];
#pragma unroll
        for (int i = 0; i < 4; ++i) v[i] = __ldg(p + i);
    } else {
#pragma unroll
        for (int i = 0; i < 4; ++i) v[i] = make_float4(0.f, 0.f, 0.f, 0.f);
    }
}

__device__ __forceinline__ void store_nA(uint2* Ap, const float4 v[4], int tid) {
    int r = tid >> 3, kt = tid & 7;
    uint2* base = Ap + kt * KTA_H + r * 4;
    base[0] = make_uint2(pack_h2(v[0].x, v[0].y), pack_h2(v[2].x, v[2].y));
    base[1] = make_uint2(pack_h2(v[0].z, v[0].w), pack_h2(v[2].z, v[2].w));
    base[2] = make_uint2(pack_h2(v[1].x, v[1].y), pack_h2(v[3].x, v[3].y));
    base[3] = make_uint2(pack_h2(v[1].z, v[1].w), pack_h2(v[3].z, v[3].w));
}

__global__ __launch_bounds__(THREADS, 2)
void gemm_node(const float* __restrict__ A,
               const float* __restrict__ W0, const float* __restrict__ W1,
               const float* __restrict__ W2, const float* __restrict__ B0,
               const float* __restrict__ B1, const float* __restrict__ B2,
               __half* __restrict__ O0, __half* __restrict__ O1,
               __half* __restrict__ O2, int M) {
    extern __shared__ uint2 smem[];
    uint2* Wp = smem;
    uint2* Ap = smem + SMEM_W_U2;
    int which = blockIdx.y;
    const float* W = (which == 0) ? W0 : (which == 1) ? W1 : W2;
    const float* bias = (which == 0) ? B0 : (which == 1) ? B1 : B2;
    __half* out = (which == 0) ? O0 : (which == 1) ? O1 : O2;

    int tid = threadIdx.x, lane = tid & 31, warp = tid >> 5;
    int wm = (warp & 3) * 16, wn = (warp >> 2) * 32;
    int g = lane >> 2, t = lane & 3;

    stage_W(Wp, W, THREADS);
    float2 bias2[4];
#pragma unroll
    for (int nf = 0; nf < 4; ++nf)
        bias2[nf] = *(const float2*)&bias[wn + nf * 8 + t * 2];

    int nTiles = (M + NTILE_M - 1) / NTILE_M;
    int tile = blockIdx.x;
    float4 cur[4];
    if (tile < nTiles) prefetch_nA(cur, A, tile * NTILE_M, M, tid);
    __syncthreads();

#pragma unroll 1
    for (; tile < nTiles; tile += gridDim.x) {
        store_nA(Ap, cur, tid);
        __syncthreads();
        int nxt = tile + gridDim.x;
        if (nxt < nTiles) prefetch_nA(cur, A, nxt * NTILE_M, M, tid);
        float c[4][4];
#pragma unroll
        for (int j = 0; j < 4; ++j)
#pragma unroll
            for (int k = 0; k < 4; ++k) c[j][k] = 0.f;
#pragma unroll
        for (int kt = 0; kt < 8; ++kt) {
            const uint2* ak = Ap + kt * KTA_H;
            const uint2* wk = Wp + kt * KTW_H;
            uint2 aA = ak[wm * 4 + lane];
            uint2 aB = ak[(wm + 8) * 4 + lane];
#pragma unroll
            for (int nf = 0; nf < 4; ++nf) {
                uint2 b = wk[(wn + nf * 8) * 4 + lane];
                mma16(c[nf], aA.x, aB.x, aA.y, aB.y, b.x, b.y);
            }
        }
        __syncthreads();
        int r0 = tile * NTILE_M + wm + g;
#pragma unroll
        for (int nf = 0; nf < 4; ++nf) {
            int col = wn + nf * 8 + t * 2;
            if (r0 < M)
                *(uint32_t*)&out[(size_t)r0 * DIM + col] =
                    pack_h2(c[nf][0] + bias2[nf].x, c[nf][1] + bias2[nf].y);
            if (r0 + 8 < M)
                *(uint32_t*)&out[(size_t)(r0 + 8) * DIM + col] =
                    pack_h2(c[nf][2] + bias2[nf].x, c[nf][3] + bias2[nf].y);
        }
    }
}

// ---------------------------------------------------------------------------
// finalize: h_out = wV / (z + 1e-6)
// ---------------------------------------------------------------------------
__global__ void finalize_kernel(float* __restrict__ hacc) {
    int i = blockIdx.x * blockDim.x + threadIdx.x;
    if (i < N_NODES * DIM) {
        int node = i >> 7;
        int head = (i >> 4) & 7;
        hacc[i] = hacc[i] / (g_z[node * HEADS + head] + 1e-6f);
    }
}

// ---------------------------------------------------------------------------
// launch
// ---------------------------------------------------------------------------
extern "C" void kernel_launch(void* const* d_in, const int* in_sizes, int n_in,
                              void* d_out, int out_size) {
    const float* h  = (const float*)d_in[0];
    const float* e  = (const float*)d_in[1];
    const int*   src = (const int*)d_in[2];
    const int*   dst = (const int*)d_in[3];
    const float* Wq = (const float*)d_in[4];
    const float* bq = (const float*)d_in[5];
    const float* Wk = (const float*)d_in[6];
    const float* bk = (const float*)d_in[7];
    const float* Wv = (const float*)d_in[8];
    const float* bv = (const float*)d_in[9];
    const float* We = (const float*)d_in[10];
    const float* be = (const float*)d_in[11];

    float* out  = (float*)d_out;
    float* hacc = out;                               // [N,H,D] accumulator -> h_out
    float* eout = out + (size_t)N_NODES * DIM;       // [E,H,D] e_out

    __half *qp, *kp, *vp;
    float *zp;
    cudaGetSymbolAddress((void**)&qp, g_Q);
    cudaGetSymbolAddress((void**)&kp, g_K);
    cudaGetSymbolAddress((void**)&vp, g_V);
    cudaGetSymbolAddress((void**)&zp, g_z);

    cudaFuncSetAttribute(gemm_node, cudaFuncAttributeMaxDynamicSharedMemorySize, NODE_SMEM);
    cudaFuncSetAttribute(gemm_edge, cudaFuncAttributeMaxDynamicSharedMemorySize, EDGE_SMEM);

    cudaMemsetAsync(hacc, 0, (size_t)N_NODES * DIM * sizeof(float));
    cudaMemsetAsync(zp, 0, (size_t)N_NODES * HEADS * sizeof(float));

    dim3 ngrid(GRID, 3);
    gemm_node<<<ngrid, THREADS, NODE_SMEM>>>(h, Wq, Wk, Wv, bq, bk, bv,
                                             qp, kp, vp, N_NODES);
    gemm_edge<<<GRID, THREADS, EDGE_SMEM>>>(e, We, be, src, dst, hacc, eout);
    finalize_kernel<<<(N_NODES * DIM + 255) / 256, 256>>>(hacc);
}